// round 1
// baseline (speedup 1.0000x reference)
#include <cuda_runtime.h>
#include <math.h>

// Problem constants
#define BSZ   4096
#define SSZ   32
#define FDIM  256
#define EDIM  256

// ------------------- scratch (device globals; no allocation) -------------------
__device__ float g_Wqk[256 * 256];      // Wq @ Wk^T  (so scores = x . (qt))
__device__ float g_bqk[256];            // bq @ Wk^T
__device__ float g_Wfused[512 * 256];   // rows 0..255: Wv@Wc_top ; rows 256..511: Wm@Wc_bot
__device__ float g_bf[256];             // bc + bv@Wc_top + bm@Wc_bot
__device__ float g_qt[4096 * 256];      // per-row folded query
__device__ float g_mm[4096 * 512];      // [ mixed_feat | mean_feat ] per row

// =====================================================================
// K0: precompute fused weight matrices.
//   blocks   0..63 : Wqk = Wq @ Wk^T          (32x32 tiles, 8x8 grid)
//   blocks  64..127: W1  = Wv @ Wc[0:256]     -> g_Wfused rows 0..255
//   blocks 128..191: W2  = Wm @ Wc[256:512]   -> g_Wfused rows 256..511
//   block  192     : bias vectors
// =====================================================================
__global__ __launch_bounds__(256) void precompute_kernel(
    const float* __restrict__ Wq, const float* __restrict__ bq,
    const float* __restrict__ Wk,
    const float* __restrict__ Wv, const float* __restrict__ bv,
    const float* __restrict__ Wm, const float* __restrict__ bm,
    const float* __restrict__ Wc, const float* __restrict__ bc)
{
    int blk = blockIdx.x;
    int tid = threadIdx.x;

    if (blk == 192) {
        __shared__ float sb[3][256];
        sb[0][tid] = bq[tid];
        sb[1][tid] = bv[tid];
        sb[2][tid] = bm[tid];
        __syncthreads();
        int j = tid;
        float aq = 0.f;
        for (int e = 0; e < 256; e++) aq += sb[0][e] * Wk[j * 256 + e];
        g_bqk[j] = aq;
        float af = bc[j];
        for (int e = 0; e < 256; e++) af += sb[1][e] * Wc[e * 256 + j];
        for (int e = 0; e < 256; e++) af += sb[2][e] * Wc[(256 + e) * 256 + j];
        g_bf[j] = af;
        return;
    }

    int mode = blk / 64;            // 0: Wqk, 1: W1, 2: W2
    int t    = blk % 64;
    int f0 = (t / 8) * 32;          // output row tile
    int j0 = (t % 8) * 32;          // output col tile

    const float* A = (mode == 0) ? Wq : (mode == 1) ? Wv : Wm;

    __shared__ float Asm[32][33];
    __shared__ float Bsm[32][33];

    int tx  = tid & 31;             // 0..31
    int ty4 = tid >> 5;             // 0..7

    float acc[4] = {0.f, 0.f, 0.f, 0.f};

    for (int e0 = 0; e0 < 256; e0 += 32) {
        #pragma unroll
        for (int r = ty4; r < 32; r += 8)
            Asm[r][tx] = A[(f0 + r) * 256 + e0 + tx];
        if (mode == 0) {
            // Bsm[j][e] = Wk[j0+j][e0+e]
            #pragma unroll
            for (int r = ty4; r < 32; r += 8)
                Bsm[r][tx] = Wk[(j0 + r) * 256 + e0 + tx];
        } else {
            const float* Wcp = Wc + (mode == 2 ? 256 * 256 : 0);
            // Bsm[e][j] = Wc[e0+e][j0+j]
            #pragma unroll
            for (int r = ty4; r < 32; r += 8)
                Bsm[r][tx] = Wcp[(e0 + r) * 256 + j0 + tx];
        }
        __syncthreads();
        if (mode == 0) {
            #pragma unroll 8
            for (int e = 0; e < 32; e++) {
                float bvv = Bsm[tx][e];
                #pragma unroll
                for (int r = 0; r < 4; r++)
                    acc[r] += Asm[ty4 + r * 8][e] * bvv;
            }
        } else {
            #pragma unroll 8
            for (int e = 0; e < 32; e++) {
                float bvv = Bsm[e][tx];
                #pragma unroll
                for (int r = 0; r < 4; r++)
                    acc[r] += Asm[ty4 + r * 8][e] * bvv;
            }
        }
        __syncthreads();
    }

    float* out = (mode == 0) ? g_Wqk : (g_Wfused + (mode == 2 ? 256 * 256 : 0));
    #pragma unroll
    for (int r = 0; r < 4; r++)
        out[(f0 + ty4 + r * 8) * 256 + j0 + tx] = acc[r];
}

// =====================================================================
// Tiled fp32 GEMM (64x64 tile, 256 threads, 4x4 per thread).
//   MODE 0: C = gather(id2feat, nodes) @ g_Wqk + g_bqk   -> g_qt   (K=256)
//   MODE 1: C = g_mm @ g_Wfused + g_bf, epilogue tanh    -> d_out  (K=512)
// N = 256 fixed. No bounds checks (all dims divide tiles).
// =====================================================================
template <int MODE>
__global__ __launch_bounds__(256) void gemm_kernel(
    const float* __restrict__ id2feat,
    const int*   __restrict__ nodes,
    float*       __restrict__ outC)
{
    constexpr int K = (MODE == 0) ? 256 : 512;
    const float* Bmat = (MODE == 0) ? g_Wqk : g_Wfused;
    const float* bias = (MODE == 0) ? g_bqk : g_bf;
    float*       C    = (MODE == 0) ? g_qt  : outC;

    int n0 = blockIdx.x * 64;
    int m0 = blockIdx.y * 64;
    int tid = threadIdx.x;

    __shared__ float As[64][17];    // [m][k], padded
    __shared__ float Bs[16][64];    // [k][n]

    // A-load mapping: thread -> (row, 4 consecutive k)
    int ar = tid >> 2;              // 0..63
    int ac = (tid & 3) * 4;         // 0,4,8,12
    const float* Arow;
    if (MODE == 0) {
        int idx = nodes[m0 + ar];
        Arow = id2feat + (long long)idx * 256;
    } else {
        Arow = g_mm + (long long)(m0 + ar) * 512;
    }

    // B-load mapping
    int br  = tid >> 4;             // 0..15
    int bc4 = (tid & 15) * 4;       // 0..60

    int tx = tid & 15;              // N dir
    int ty = tid >> 4;              // M dir

    float acc[4][4];
    #pragma unroll
    for (int i = 0; i < 4; i++)
        #pragma unroll
        for (int j = 0; j < 4; j++) acc[i][j] = 0.f;

    for (int k0 = 0; k0 < K; k0 += 16) {
        float4 va = *reinterpret_cast<const float4*>(Arow + k0 + ac);
        As[ar][ac + 0] = va.x;
        As[ar][ac + 1] = va.y;
        As[ar][ac + 2] = va.z;
        As[ar][ac + 3] = va.w;
        float4 vb = *reinterpret_cast<const float4*>(Bmat + (long long)(k0 + br) * 256 + n0 + bc4);
        *reinterpret_cast<float4*>(&Bs[br][bc4]) = vb;
        __syncthreads();

        #pragma unroll
        for (int kk = 0; kk < 16; kk++) {
            float a[4];
            #pragma unroll
            for (int i = 0; i < 4; i++) a[i] = As[ty * 4 + i][kk];
            float4 b4 = *reinterpret_cast<const float4*>(&Bs[kk][tx * 4]);
            #pragma unroll
            for (int i = 0; i < 4; i++) {
                acc[i][0] += a[i] * b4.x;
                acc[i][1] += a[i] * b4.y;
                acc[i][2] += a[i] * b4.z;
                acc[i][3] += a[i] * b4.w;
            }
        }
        __syncthreads();
    }

    float4 bb = *reinterpret_cast<const float4*>(bias + n0 + tx * 4);
    #pragma unroll
    for (int i = 0; i < 4; i++) {
        float4 v;
        v.x = acc[i][0] + bb.x;
        v.y = acc[i][1] + bb.y;
        v.z = acc[i][2] + bb.z;
        v.w = acc[i][3] + bb.w;
        if (MODE == 1) {
            v.x = tanhf(v.x); v.y = tanhf(v.y);
            v.z = tanhf(v.z); v.w = tanhf(v.w);
        }
        *reinterpret_cast<float4*>(C + (long long)(m0 + ty * 4 + i) * 256 + n0 + tx * 4) = v;
    }
}

// =====================================================================
// K2: per-batch-row attention + mean aggregation.
// One block per b. 256 threads.
//   scores[s] = x_attn[s] . qt[b]    (8 warps x 4 rows, rows stashed in smem)
//   softmax over 32 (self slot is masked in the reference -> neighbors only)
//   mixed = sum_s w[s] x_attn[s]  -> g_mm[b][0:256]
//   meanf = mean_s x_mean[s]      -> g_mm[b][256:512]
// =====================================================================
__global__ __launch_bounds__(256) void attn_mean_kernel(
    const int*   __restrict__ neigh_mean,
    const int*   __restrict__ neigh_attn,
    const float* __restrict__ id2feat)
{
    int b    = blockIdx.x;
    int tid  = threadIdx.x;
    int lane = tid & 31;
    int warp = tid >> 5;

    __shared__ float rows[32][256];
    __shared__ float qts[256];
    __shared__ float sc[32];

    qts[tid] = g_qt[b * 256 + tid];
    __syncthreads();

    // preload qt fragment for this lane
    float qreg[8];
    #pragma unroll
    for (int i = 0; i < 8; i++) qreg[i] = qts[lane + 32 * i];

    // scores + stash attn rows
    #pragma unroll
    for (int r = 0; r < 4; r++) {
        int s = warp * 4 + r;
        int idx = neigh_attn[b * 32 + s];
        const float* row = id2feat + (long long)idx * 256;
        float acc = 0.f;
        #pragma unroll
        for (int i = 0; i < 8; i++) {
            float v = row[lane + 32 * i];
            rows[s][lane + 32 * i] = v;
            acc += v * qreg[i];
        }
        #pragma unroll
        for (int o = 16; o; o >>= 1)
            acc += __shfl_xor_sync(0xffffffff, acc, o);
        if (lane == 0) sc[s] = acc;
    }

    // mean aggregation (independent of scores)
    float macc = 0.f;
    #pragma unroll 8
    for (int s = 0; s < 32; s++) {
        int idx = neigh_mean[b * 32 + s];
        macc += id2feat[(long long)idx * 256 + tid];
    }
    g_mm[(long long)b * 512 + 256 + tid] = macc * (1.f / 32.f);

    __syncthreads();

    // softmax over 32 scores (warp 0)
    if (warp == 0) {
        float v = sc[lane];
        float m = v;
        #pragma unroll
        for (int o = 16; o; o >>= 1)
            m = fmaxf(m, __shfl_xor_sync(0xffffffff, m, o));
        float e = expf(v - m);
        float sum = e;
        #pragma unroll
        for (int o = 16; o; o >>= 1)
            sum += __shfl_xor_sync(0xffffffff, sum, o);
        sc[lane] = e / sum;
    }
    __syncthreads();

    // weighted feature sum
    float acc = 0.f;
    #pragma unroll
    for (int s = 0; s < 32; s++) acc += sc[s] * rows[s][tid];
    g_mm[(long long)b * 512 + tid] = acc;
}

// =====================================================================
// K4: row-wise L2 normalize (in place on d_out). One warp per row.
// =====================================================================
__global__ __launch_bounds__(256) void normalize_kernel(float* __restrict__ out)
{
    int row  = blockIdx.x * 8 + (threadIdx.x >> 5);
    int lane = threadIdx.x & 31;
    float v[8];
    float ss = 0.f;
    #pragma unroll
    for (int i = 0; i < 8; i++) {
        v[i] = out[(long long)row * 256 + lane + 32 * i];
        ss += v[i] * v[i];
    }
    #pragma unroll
    for (int o = 16; o; o >>= 1)
        ss += __shfl_xor_sync(0xffffffff, ss, o);
    float scale = 1.f / fmaxf(sqrtf(ss), 1e-12f);
    #pragma unroll
    for (int i = 0; i < 8; i++)
        out[(long long)row * 256 + lane + 32 * i] = v[i] * scale;
}

// =====================================================================
extern "C" void kernel_launch(void* const* d_in, const int* in_sizes, int n_in,
                              void* d_out, int out_size)
{
    const int*   nodes      = (const int*)  d_in[0];
    const int*   neigh_mean = (const int*)  d_in[1];
    const int*   neigh_attn = (const int*)  d_in[2];
    const float* id2feat    = (const float*)d_in[3];
    const float* Wm         = (const float*)d_in[4];
    const float* bm         = (const float*)d_in[5];
    const float* Wq         = (const float*)d_in[6];
    const float* bq         = (const float*)d_in[7];
    const float* Wk         = (const float*)d_in[8];
    // d_in[9] = bk : drops out of softmax (constant shift per row), unused
    const float* Wv         = (const float*)d_in[10];
    const float* bv         = (const float*)d_in[11];
    const float* Wc         = (const float*)d_in[12];
    const float* bc         = (const float*)d_in[13];
    float* out = (float*)d_out;

    precompute_kernel<<<193, 256>>>(Wq, bq, Wk, Wv, bv, Wm, bm, Wc, bc);
    gemm_kernel<0><<<dim3(4, 64), 256>>>(id2feat, nodes, nullptr);
    attn_mean_kernel<<<4096, 256>>>(neigh_mean, neigh_attn, id2feat);
    gemm_kernel<1><<<dim3(4, 64), 256>>>(nullptr, nullptr, out);
    normalize_kernel<<<512, 256>>>(out);
}

// round 3
// speedup vs baseline: 1.0563x; 1.0563x over previous
#include <cuda_runtime.h>
#include <cstdint>
#include <math.h>

// Problem constants
#define BSZ   4096
#define SSZ   32
#define FDIM  256
#define EDIM  256

// ------------------- scratch (device globals; no allocation) -------------------
// Weights pre-split into tf32 hi/lo, stored [n][k] with k interleaved in groups
// of 8 as [0,4,1,5,2,6,3,7] (pairs (k,k+4) adjacent -> LDS.64 fragment loads).
__device__ float g_B0Hi[256 * 256];     // Wq@Wk^T   (K=256)
__device__ float g_B0Lo[256 * 256];
__device__ float g_B1Hi[256 * 512];     // [Wv@Wc_top ; Wm@Wc_bot]  (K=512)
__device__ float g_B1Lo[256 * 512];
__device__ float g_bqk[256];            // bq @ Wk^T
__device__ float g_bf[256];             // bc + bv@Wc_top + bm@Wc_bot
__device__ float g_qt[4096 * 256];      // per-row folded query
__device__ float g_mm[4096 * 512];      // [ mixed_feat | mean_feat ] per row

__device__ __forceinline__ float trunc_tf32(float x) {
    return __uint_as_float(__float_as_uint(x) & 0xFFFFE000u);
}
__device__ __forceinline__ int intl8(int k) {
    return (k & ~7) | ((k & 3) << 1) | ((k >> 2) & 1);
}
__device__ __forceinline__ void cp16(void* s, const void* g) {
    uint32_t sa = (uint32_t)__cvta_generic_to_shared(s);
    asm volatile("cp.async.cg.shared.global [%0], [%1], 16;\n" :: "r"(sa), "l"(g));
}
__device__ __forceinline__ void mma8(float* c, const uint32_t* a, const uint32_t* b) {
    asm volatile(
        "mma.sync.aligned.m16n8k8.row.col.f32.tf32.tf32.f32 "
        "{%0,%1,%2,%3}, {%4,%5,%6,%7}, {%8,%9}, {%0,%1,%2,%3};"
        : "+f"(c[0]), "+f"(c[1]), "+f"(c[2]), "+f"(c[3])
        : "r"(a[0]), "r"(a[1]), "r"(a[2]), "r"(a[3]), "r"(b[0]), "r"(b[1]));
}

// =====================================================================
// K0: precompute fused weight matrices (split + interleaved store).
//   blocks   0..63 : Wqk = Wq @ Wk^T          -> g_B0 (k rows 0..255)
//   blocks  64..127: W1  = Wv @ Wc[0:256]     -> g_B1 k rows 0..255
//   blocks 128..191: W2  = Wm @ Wc[256:512]   -> g_B1 k rows 256..511
//   block  192     : bias vectors
// =====================================================================
__global__ __launch_bounds__(256) void precompute_kernel(
    const float* __restrict__ Wq, const float* __restrict__ bq,
    const float* __restrict__ Wk,
    const float* __restrict__ Wv, const float* __restrict__ bv,
    const float* __restrict__ Wm, const float* __restrict__ bm,
    const float* __restrict__ Wc, const float* __restrict__ bc)
{
    int blk = blockIdx.x;
    int tid = threadIdx.x;

    if (blk == 192) {
        __shared__ float sb[3][256];
        sb[0][tid] = bq[tid];
        sb[1][tid] = bv[tid];
        sb[2][tid] = bm[tid];
        __syncthreads();
        int j = tid;
        float aq = 0.f;
        for (int e = 0; e < 256; e++) aq += sb[0][e] * Wk[j * 256 + e];
        g_bqk[j] = aq;
        float af = bc[j];
        for (int e = 0; e < 256; e++) af += sb[1][e] * Wc[e * 256 + j];
        for (int e = 0; e < 256; e++) af += sb[2][e] * Wc[(256 + e) * 256 + j];
        g_bf[j] = af;
        return;
    }

    int mode = blk / 64;            // 0: Wqk, 1: W1, 2: W2
    int t    = blk % 64;
    int f0 = (t / 8) * 32;          // k tile
    int j0 = (t % 8) * 32;          // n tile

    const float* A = (mode == 0) ? Wq : (mode == 1) ? Wv : Wm;

    __shared__ float Asm[32][33];
    __shared__ float Bsm[32][33];

    int tx  = tid & 31;
    int ty4 = tid >> 5;

    float acc[4] = {0.f, 0.f, 0.f, 0.f};

    for (int e0 = 0; e0 < 256; e0 += 32) {
        #pragma unroll
        for (int r = ty4; r < 32; r += 8)
            Asm[r][tx] = A[(f0 + r) * 256 + e0 + tx];
        if (mode == 0) {
            #pragma unroll
            for (int r = ty4; r < 32; r += 8)
                Bsm[r][tx] = Wk[(j0 + r) * 256 + e0 + tx];
        } else {
            const float* Wcp = Wc + (mode == 2 ? 256 * 256 : 0);
            #pragma unroll
            for (int r = ty4; r < 32; r += 8)
                Bsm[r][tx] = Wcp[(e0 + r) * 256 + j0 + tx];
        }
        __syncthreads();
        if (mode == 0) {
            #pragma unroll 8
            for (int e = 0; e < 32; e++) {
                float bvv = Bsm[tx][e];
                #pragma unroll
                for (int r = 0; r < 4; r++)
                    acc[r] += Asm[ty4 + r * 8][e] * bvv;
            }
        } else {
            #pragma unroll 8
            for (int e = 0; e < 32; e++) {
                float bvv = Bsm[e][tx];
                #pragma unroll
                for (int r = 0; r < 4; r++)
                    acc[r] += Asm[ty4 + r * 8][e] * bvv;
            }
        }
        __syncthreads();
    }

    #pragma unroll
    for (int r = 0; r < 4; r++) {
        int krow = f0 + ty4 + r * 8;
        int ncol = j0 + tx;
        float v  = acc[r];
        float vh = trunc_tf32(v);
        float vl = trunc_tf32(v - vh);
        if (mode == 0) {
            int idx = ncol * 256 + intl8(krow);
            g_B0Hi[idx] = vh; g_B0Lo[idx] = vl;
        } else {
            int k = krow + (mode == 2 ? 256 : 0);
            int idx = ncol * 512 + intl8(k);
            g_B1Hi[idx] = vh; g_B1Lo[idx] = vl;
        }
    }
}

// =====================================================================
// Tensor-core tf32 GEMM, 3xTF32 split precision.
// Block 128 threads (4 warps 2x2), tile 64(M)x64(N), k-chunk 32, double
// buffered cp.async for B, register-staged split-convert for A.
//   MODE 0: C = gather(id2feat, nodes) @ B0 + bqk         -> g_qt  (K=256)
//   MODE 1: C = g_mm @ B1 + bf, epilogue tanh             -> out   (K=512)
// Dynamic smem 64KB: per buffer {AsHi[64*32] AsLo BsHi[64*32] BsLo}.
// =====================================================================
template <int MODE>
__global__ __launch_bounds__(128) void gemm_tc(
    const float* __restrict__ id2feat,
    const int*   __restrict__ nodes,
    float*       __restrict__ outC)
{
    constexpr int K = (MODE == 0) ? 256 : 512;
    constexpr int S = K / 32;
    const float* gBH  = (MODE == 0) ? g_B0Hi : g_B1Hi;
    const float* gBL  = (MODE == 0) ? g_B0Lo : g_B1Lo;
    const float* bias = (MODE == 0) ? g_bqk  : g_bf;
    float*       C    = (MODE == 0) ? g_qt   : outC;

    extern __shared__ float sm[];
    int tid  = threadIdx.x;
    int lane = tid & 31;
    int wid  = tid >> 5;
    int warpM = wid & 1, warpN = wid >> 1;
    int n0 = blockIdx.x * 64, m0 = blockIdx.y * 64;

    // A staging mapping: thread -> (row am, 16-wide k half kh)
    int am = tid >> 1;
    int kh = (tid & 1) * 16;
    const float* Arow;
    if (MODE == 0) Arow = id2feat + (long long)nodes[m0 + am] * 256;
    else           Arow = g_mm + (long long)(m0 + am) * 512;
    int swA = (am & 3) << 3;

    // B staging mapping: thread -> (row bn, 4 of 8 16B chunks)
    int bn = tid >> 1;
    int jb = (tid & 1) * 4;
    const float* gBHrow = gBH + (long long)(n0 + bn) * K;
    const float* gBLrow = gBL + (long long)(n0 + bn) * K;
    int swB = (bn & 3) << 1;

    float4 va0, va1, va2, va3;

    float acc[2][4][4];
    #pragma unroll
    for (int mi = 0; mi < 2; mi++)
        #pragma unroll
        for (int ni = 0; ni < 4; ni++)
            #pragma unroll
            for (int q = 0; q < 4; q++) acc[mi][ni][q] = 0.f;

    auto loadA = [&](int k0) {
        const float4* p = (const float4*)(Arow + k0 + kh);
        va0 = p[0]; va1 = p[1]; va2 = p[2]; va3 = p[3];
    };
    auto storeA = [&](int buf) {
        float v[16] = {va0.x, va0.y, va0.z, va0.w, va1.x, va1.y, va1.z, va1.w,
                       va2.x, va2.y, va2.z, va2.w, va3.x, va3.y, va3.z, va3.w};
        float* AH = sm + buf * 8192;
        float* AL = AH + 2048;
        #pragma unroll
        for (int g2 = 0; g2 < 2; g2++)
            #pragma unroll
            for (int c = 0; c < 4; c++) {
                float x0 = v[g2 * 8 + c], x1 = v[g2 * 8 + c + 4];
                float h0 = trunc_tf32(x0), h1 = trunc_tf32(x1);
                float l0 = trunc_tf32(x0 - h0), l1 = trunc_tf32(x1 - h1);
                int o  = kh + g2 * 8 + 2 * c;
                int ph = o ^ swA;
                *(float2*)(AH + am * 32 + ph) = make_float2(h0, h1);
                *(float2*)(AL + am * 32 + ph) = make_float2(l0, l1);
            }
    };
    auto loadB = [&](int s, int buf) {
        float* BH = sm + buf * 8192 + 4096;
        float* BL = BH + 2048;
        int k0 = s * 32;
        #pragma unroll
        for (int jj = 0; jj < 4; jj++) {
            int j = jb + jj;
            int p = j ^ swB;
            cp16(BH + bn * 32 + p * 4, gBHrow + k0 + j * 4);
            cp16(BL + bn * 32 + p * 4, gBLrow + k0 + j * 4);
        }
    };

    // prologue: stage 0
    loadA(0);
    storeA(0);
    loadB(0, 0);
    asm volatile("cp.async.commit_group;");

    for (int s = 0; s < S; s++) {
        int buf = s & 1;
        bool more = (s + 1 < S);
        if (more) {
            loadA((s + 1) * 32);
            loadB(s + 1, buf ^ 1);
            asm volatile("cp.async.commit_group;");
            asm volatile("cp.async.wait_group 1;");
        } else {
            asm volatile("cp.async.wait_group 0;");
        }
        __syncthreads();

        const float* AH = sm + buf * 8192;
        const float* AL = AH + 2048;
        const float* BH = AH + 4096;
        const float* BL = AH + 6144;

        #pragma unroll
        for (int kk = 0; kk < 4; kk++) {
            int o = kk * 8 + 2 * (lane & 3);
            uint2 aH[2][2], aL[2][2];
            #pragma unroll
            for (int mi = 0; mi < 2; mi++) {
                int r  = warpM * 32 + mi * 16 + (lane >> 2);
                int px = o ^ ((r & 3) << 3);
                aH[mi][0] = *(const uint2*)(AH + r * 32 + px);
                aH[mi][1] = *(const uint2*)(AH + (r + 8) * 32 + px);
                aL[mi][0] = *(const uint2*)(AL + r * 32 + px);
                aL[mi][1] = *(const uint2*)(AL + (r + 8) * 32 + px);
            }
            uint2 bH[4], bL[4];
            #pragma unroll
            for (int ni = 0; ni < 4; ni++) {
                int n  = warpN * 32 + ni * 8 + (lane >> 2);
                int px = o ^ ((n & 3) << 3);
                bH[ni] = *(const uint2*)(BH + n * 32 + px);
                bL[ni] = *(const uint2*)(BL + n * 32 + px);
            }
            #pragma unroll
            for (int mi = 0; mi < 2; mi++) {
                uint32_t Ah[4] = {aH[mi][0].x, aH[mi][1].x, aH[mi][0].y, aH[mi][1].y};
                uint32_t Al[4] = {aL[mi][0].x, aL[mi][1].x, aL[mi][0].y, aL[mi][1].y};
                #pragma unroll
                for (int ni = 0; ni < 4; ni++) {
                    uint32_t Bh[2] = {bH[ni].x, bH[ni].y};
                    uint32_t Bl[2] = {bL[ni].x, bL[ni].y};
                    mma8(acc[mi][ni], Ah, Bh);
                    mma8(acc[mi][ni], Ah, Bl);
                    mma8(acc[mi][ni], Al, Bh);
                }
            }
        }
        if (more) storeA(buf ^ 1);
    }

    // epilogue
    #pragma unroll
    for (int mi = 0; mi < 2; mi++) {
        #pragma unroll
        for (int ni = 0; ni < 4; ni++) {
            int rg = m0 + warpM * 32 + mi * 16 + (lane >> 2);
            int cg = n0 + warpN * 32 + ni * 8 + 2 * (lane & 3);
            float2 bb = *(const float2*)(bias + cg);
            float o0 = acc[mi][ni][0] + bb.x;
            float o1 = acc[mi][ni][1] + bb.y;
            float o2 = acc[mi][ni][2] + bb.x;
            float o3 = acc[mi][ni][3] + bb.y;
            if (MODE == 1) {
                o0 = tanhf(o0); o1 = tanhf(o1);
                o2 = tanhf(o2); o3 = tanhf(o3);
            }
            *(float2*)(C + (long long)rg * 256 + cg)       = make_float2(o0, o1);
            *(float2*)(C + (long long)(rg + 8) * 256 + cg) = make_float2(o2, o3);
        }
    }
}

// =====================================================================
// K2: per-batch-row attention + mean aggregation.
// =====================================================================
__global__ __launch_bounds__(256) void attn_mean_kernel(
    const int*   __restrict__ neigh_mean,
    const int*   __restrict__ neigh_attn,
    const float* __restrict__ id2feat)
{
    int b    = blockIdx.x;
    int tid  = threadIdx.x;
    int lane = tid & 31;
    int warp = tid >> 5;

    __shared__ float rows[32][256];
    __shared__ float qts[256];
    __shared__ float sc[32];

    qts[tid] = g_qt[b * 256 + tid];
    __syncthreads();

    float qreg[8];
    #pragma unroll
    for (int i = 0; i < 8; i++) qreg[i] = qts[lane + 32 * i];

    #pragma unroll
    for (int r = 0; r < 4; r++) {
        int s = warp * 4 + r;
        int idx = neigh_attn[b * 32 + s];
        const float* row = id2feat + (long long)idx * 256;
        float acc = 0.f;
        #pragma unroll
        for (int i = 0; i < 8; i++) {
            float v = row[lane + 32 * i];
            rows[s][lane + 32 * i] = v;
            acc += v * qreg[i];
        }
        #pragma unroll
        for (int o = 16; o; o >>= 1)
            acc += __shfl_xor_sync(0xffffffff, acc, o);
        if (lane == 0) sc[s] = acc;
    }

    float macc = 0.f;
    #pragma unroll 8
    for (int s = 0; s < 32; s++) {
        int idx = neigh_mean[b * 32 + s];
        macc += id2feat[(long long)idx * 256 + tid];
    }
    g_mm[(long long)b * 512 + 256 + tid] = macc * (1.f / 32.f);

    __syncthreads();

    if (warp == 0) {
        float v = sc[lane];
        float m = v;
        #pragma unroll
        for (int o = 16; o; o >>= 1)
            m = fmaxf(m, __shfl_xor_sync(0xffffffff, m, o));
        float e = expf(v - m);
        float sum = e;
        #pragma unroll
        for (int o = 16; o; o >>= 1)
            sum += __shfl_xor_sync(0xffffffff, sum, o);
        sc[lane] = e / sum;
    }
    __syncthreads();

    float acc = 0.f;
    #pragma unroll
    for (int s = 0; s < 32; s++) acc += sc[s] * rows[s][tid];
    g_mm[(long long)b * 512 + tid] = acc;
}

// =====================================================================
// K4: row-wise L2 normalize (in place on d_out). One warp per row.
// =====================================================================
__global__ __launch_bounds__(256) void normalize_kernel(float* __restrict__ out)
{
    int row  = blockIdx.x * 8 + (threadIdx.x >> 5);
    int lane = threadIdx.x & 31;
    float v[8];
    float ss = 0.f;
    #pragma unroll
    for (int i = 0; i < 8; i++) {
        v[i] = out[(long long)row * 256 + lane + 32 * i];
        ss += v[i] * v[i];
    }
    #pragma unroll
    for (int o = 16; o; o >>= 1)
        ss += __shfl_xor_sync(0xffffffff, ss, o);
    float scale = 1.f / fmaxf(sqrtf(ss), 1e-12f);
    #pragma unroll
    for (int i = 0; i < 8; i++)
        out[(long long)row * 256 + lane + 32 * i] = v[i] * scale;
}

// =====================================================================
extern "C" void kernel_launch(void* const* d_in, const int* in_sizes, int n_in,
                              void* d_out, int out_size)
{
    const int*   nodes      = (const int*)  d_in[0];
    const int*   neigh_mean = (const int*)  d_in[1];
    const int*   neigh_attn = (const int*)  d_in[2];
    const float* id2feat    = (const float*)d_in[3];
    const float* Wm         = (const float*)d_in[4];
    const float* bm         = (const float*)d_in[5];
    const float* Wq         = (const float*)d_in[6];
    const float* bq         = (const float*)d_in[7];
    const float* Wk         = (const float*)d_in[8];
    // d_in[9] = bk : drops out of softmax (constant shift per row), unused
    const float* Wv         = (const float*)d_in[10];
    const float* bv         = (const float*)d_in[11];
    const float* Wc         = (const float*)d_in[12];
    const float* bc         = (const float*)d_in[13];
    float* out = (float*)d_out;

    cudaFuncSetAttribute(gemm_tc<0>, cudaFuncAttributeMaxDynamicSharedMemorySize, 65536);
    cudaFuncSetAttribute(gemm_tc<1>, cudaFuncAttributeMaxDynamicSharedMemorySize, 65536);

    precompute_kernel<<<193, 256>>>(Wq, bq, Wk, Wv, bv, Wm, bm, Wc, bc);
    gemm_tc<0><<<dim3(4, 64), 128, 65536>>>(id2feat, nodes, nullptr);
    attn_mean_kernel<<<4096, 256>>>(neigh_mean, neigh_attn, id2feat);
    gemm_tc<1><<<dim3(4, 64), 128, 65536>>>(nullptr, nullptr, out);
    normalize_kernel<<<512, 256>>>(out);
}